// round 10
// baseline (speedup 1.0000x reference)
#include <cuda_runtime.h>
#include <stdint.h>

#define N_SENS 10000
#define N_HID  400000
#define N_MOT  1000
#define E_SH   4000000
#define E_HH   16000000
#define E_HM   400000

#define SENS_WORDS 313      // ceil(10000/32)
#define HID_WORDS  12500    // 400000/32

#define G_SH (E_SH / 4)     // 1,000,000 int4 groups
#define G_HH (E_HH / 4)     // 4,000,000
#define G_HM (E_HM / 4)     // 100,000

#define EGRID 592           // 148 SMs x 4 blocks, all co-resident
#define ETPB  512
#define ENT   (EGRID * ETPB)
#define N_HH_BLK 474        // 474:118 ~= 192MB:48MB byte ratio
#define N_SH_BLK (EGRID - N_HH_BLK)

#define TGRID 592
#define TTPB  256
#define TNT   (TGRID * TTPB)

// Scratch (__device__ globals; allocation-free rule)
__device__ uint32_t g_sens_bits[SENS_WORDS];
__device__ uint32_t g_hid_bits[HID_WORDS];
__device__ float    g_hid_in[N_HID];
__device__ float    g_mot_in[N_MOT];
// Monotonic ticket barriers (never reset; grow across graph replays)
__device__ unsigned long long g_bar_e;   // edges kernel: init -> edge phase
__device__ unsigned long long g_bar_t;   // tail kernel:  hm   -> motor

__device__ __forceinline__ void grid_barrier(unsigned long long* bar, int nblk) {
    __syncthreads();
    if (threadIdx.x == 0) {
        __threadfence();
        unsigned long long ticket = atomicAdd(bar, 1ULL);
        unsigned long long target = (ticket / nblk + 1ULL) * (unsigned long long)nblk;
        while (*(volatile unsigned long long*)bar < target) { }
        __threadfence();
    }
    __syncthreads();
}

// ---------------------------------------------------------------------------
// K1: fused init + role-split edge phase.
//   Phase A (all blocks): zero accumulators, build spike bitmasks.
//   Grid barrier (592 blocks, 4/SM guaranteed co-resident).
//   Phase B: 474 blocks stream HH, 118 blocks stream SH (dense streaming,
//   3 independent LDG.128/iter, smem bitmask gates predicated atomics).
// ---------------------------------------------------------------------------
__global__ void __launch_bounds__(ETPB, 4)
k_edges(const float* __restrict__ s_in,
        const float* __restrict__ s_mem,
        const float* __restrict__ prev_spk,
        const int4* __restrict__ sh_pre,
        const int4* __restrict__ sh_post,
        const float4* __restrict__ sh_w,
        const int4* __restrict__ hh_pre,
        const int4* __restrict__ hh_post,
        const float4* __restrict__ hh_w) {
    extern __shared__ uint32_t bits[];     // 50 KB
    const int b = blockIdx.x;
    const int tid = b * ETPB + threadIdx.x;

    // -------- Phase A: init (400128 and 10016 are multiples of 32;
    //          ENT is a multiple of 32 -> warps stay converged for ballot)
    for (int i = tid; i < 400128; i += ENT) {
        if (i < N_HID) g_hid_in[i] = 0.0f;
        if (i < N_MOT) g_mot_in[i] = 0.0f;

        int predh = (i < N_HID) ? (prev_spk[i] != 0.0f) : 0;
        uint32_t bh = __ballot_sync(0xFFFFFFFFu, predh);
        if ((i & 31) == 0 && (i >> 5) < HID_WORDS) g_hid_bits[i >> 5] = bh;

        if (i < 10016) {
            int preds = 0;
            if (i < N_SENS) {
                float m = 0.9f * s_mem[i] + 5.0f * s_in[i];
                preds = (m > 1.0f);
            }
            uint32_t bs = __ballot_sync(0xFFFFFFFFu, preds);
            if ((i & 31) == 0 && (i >> 5) < SENS_WORDS) g_sens_bits[i >> 5] = bs;
        }
    }

    grid_barrier(&g_bar_e, EGRID);

    // -------- Phase B: role-split dense edge streaming
    const bool is_hh = (b < N_HH_BLK);

    if (is_hh) {
        for (int i = threadIdx.x; i < HID_WORDS; i += blockDim.x)
            bits[i] = g_hid_bits[i];
        __syncthreads();

        const int stride = N_HH_BLK * ETPB;
        for (int t = b * ETPB + threadIdx.x; t < G_HH; t += stride) {
            int4 p = __ldcs(&hh_pre[t]);
            int4 q = __ldcs(&hh_post[t]);
            float4 wv = __ldcs(&hh_w[t]);
            uint32_t b0 = (bits[p.x >> 5] >> (p.x & 31)) & 1u;
            uint32_t b1 = (bits[p.y >> 5] >> (p.y & 31)) & 1u;
            uint32_t b2 = (bits[p.z >> 5] >> (p.z & 31)) & 1u;
            uint32_t b3 = (bits[p.w >> 5] >> (p.w & 31)) & 1u;
            if (b0) atomicAdd(&g_hid_in[q.x], 0.5f * wv.x);
            if (b1) atomicAdd(&g_hid_in[q.y], 0.5f * wv.y);
            if (b2) atomicAdd(&g_hid_in[q.z], 0.5f * wv.z);
            if (b3) atomicAdd(&g_hid_in[q.w], 0.5f * wv.w);
        }
    } else {
        for (int i = threadIdx.x; i < SENS_WORDS; i += blockDim.x)
            bits[i] = g_sens_bits[i];
        __syncthreads();

        const int rank = b - N_HH_BLK;                // 0..117
        const int stride = N_SH_BLK * ETPB;
        for (int t = rank * ETPB + threadIdx.x; t < G_SH; t += stride) {
            int4 p = __ldcs(&sh_pre[t]);
            int4 q = __ldcs(&sh_post[t]);
            float4 wv = __ldcs(&sh_w[t]);
            uint32_t b0 = (bits[p.x >> 5] >> (p.x & 31)) & 1u;
            uint32_t b1 = (bits[p.y >> 5] >> (p.y & 31)) & 1u;
            uint32_t b2 = (bits[p.z >> 5] >> (p.z & 31)) & 1u;
            uint32_t b3 = (bits[p.w >> 5] >> (p.w & 31)) & 1u;
            if (b0) atomicAdd(&g_hid_in[q.x], wv.x);
            if (b1) atomicAdd(&g_hid_in[q.y], wv.y);
            if (b2) atomicAdd(&g_hid_in[q.z], wv.z);
            if (b3) atomicAdd(&g_hid_in[q.w], wv.w);
        }
    }
}

// ---------------------------------------------------------------------------
// K2: fused tail — HM scatter (inline hidden spike) ; barrier ; motor LIF.
// ---------------------------------------------------------------------------
__global__ void __launch_bounds__(TTPB)
k_tail(const float* __restrict__ h_mem,
       const float* __restrict__ m_mem,
       const int4* __restrict__ pre,
       const int4* __restrict__ post,
       const float4* __restrict__ w,
       float* __restrict__ out) {
    const int tid = blockIdx.x * blockDim.x + threadIdx.x;

    for (int t = tid; t < G_HM; t += TNT) {
        int4 p = __ldcs(&pre[t]);
        int4 q = __ldcs(&post[t]);
        float4 wv = __ldcs(&w[t]);
        bool s0 = 0.9f * __ldg(&h_mem[p.x]) + 5.0f * g_hid_in[p.x] > 1.0f;
        bool s1 = 0.9f * __ldg(&h_mem[p.y]) + 5.0f * g_hid_in[p.y] > 1.0f;
        bool s2 = 0.9f * __ldg(&h_mem[p.z]) + 5.0f * g_hid_in[p.z] > 1.0f;
        bool s3 = 0.9f * __ldg(&h_mem[p.w]) + 5.0f * g_hid_in[p.w] > 1.0f;
        if (s0) atomicAdd(&g_mot_in[q.x], wv.x);
        if (s1) atomicAdd(&g_mot_in[q.y], wv.y);
        if (s2) atomicAdd(&g_mot_in[q.z], wv.z);
        if (s3) atomicAdd(&g_mot_in[q.w], wv.w);
    }

    grid_barrier(&g_bar_t, TGRID);

    for (int i = tid; i < N_MOT; i += TNT) {
        float m = 0.9f * __ldg(&m_mem[i]) + 20.0f * g_mot_in[i];
        out[i] = (m > 1.0f) ? 1.0f : 0.0f;
    }
}

extern "C" void kernel_launch(void* const* d_in, const int* in_sizes, int n_in,
                              void* d_out, int out_size) {
    const float* sensory_input     = (const float*)d_in[0];
    const float* sensory_mem       = (const float*)d_in[1];
    const float* hidden_mem        = (const float*)d_in[2];
    const float* motor_mem         = (const float*)d_in[3];
    const float* hidden_prev_spike = (const float*)d_in[4];
    const float* w_sh              = (const float*)d_in[5];
    const float* w_hh              = (const float*)d_in[6];
    const float* w_hm              = (const float*)d_in[7];
    const int*   sh_pre            = (const int*)d_in[8];
    const int*   sh_post           = (const int*)d_in[9];
    const int*   hh_pre            = (const int*)d_in[10];
    const int*   hh_post           = (const int*)d_in[11];
    const int*   hm_pre            = (const int*)d_in[12];
    const int*   hm_post           = (const int*)d_in[13];
    float* out = (float*)d_out;

    static bool once = false;
    const int smem = HID_WORDS * sizeof(uint32_t);  // 50000 bytes
    if (!once) {
        cudaFuncSetAttribute(k_edges,
                             cudaFuncAttributeMaxDynamicSharedMemorySize, smem);
        once = true;
    }

    k_edges<<<EGRID, ETPB, smem>>>(
        sensory_input, sensory_mem, hidden_prev_spike,
        (const int4*)sh_pre, (const int4*)sh_post, (const float4*)w_sh,
        (const int4*)hh_pre, (const int4*)hh_post, (const float4*)w_hh);

    k_tail<<<TGRID, TTPB>>>(hidden_mem, motor_mem,
                            (const int4*)hm_pre, (const int4*)hm_post,
                            (const float4*)w_hm, out);
}

// round 11
// speedup vs baseline: 1.6542x; 1.6542x over previous
#include <cuda_runtime.h>
#include <stdint.h>

#define N_SENS 10000
#define N_HID  400000
#define N_MOT  1000
#define E_SH   4000000
#define E_HH   16000000
#define E_HM   400000

#define SENS_WORDS 313      // ceil(10000/32)
#define HID_WORDS  12500    // 400000/32

#define G_SH (E_SH / 4)     // 1,000,000 int4 groups
#define G_HH (E_HH / 4)     // 4,000,000

#define EGRID 592           // 148 SMs x 4 blocks, all co-resident
#define ETPB  512
#define N_HH_BLK 474        // 474:118 ~= 192MB:48MB byte ratio
#define N_SH_BLK (EGRID - N_HH_BLK)

// Scratch (__device__ globals; allocation-free rule)
__device__ uint32_t g_sens_bits[SENS_WORDS];
__device__ uint32_t g_hid_bits[HID_WORDS];
__device__ float    g_hid_in[N_HID];
__device__ float    g_mot_in[N_MOT];

// ---------------------------------------------------------------------------
// K1: zero accumulators, build sensory + hidden-prev spike bitmasks
// ---------------------------------------------------------------------------
__global__ void k_init(const float* __restrict__ s_in,
                       const float* __restrict__ s_mem,
                       const float* __restrict__ prev_spk) {
    int i = blockIdx.x * blockDim.x + threadIdx.x;

    if (i < N_HID) g_hid_in[i] = 0.0f;
    if (i < N_MOT) g_mot_in[i] = 0.0f;

    {   // hidden prev-spike bitmask (grid is multiple of 32 threads)
        int pred = (i < N_HID) ? (prev_spk[i] != 0.0f) : 0;
        uint32_t bits = __ballot_sync(0xFFFFFFFFu, pred);
        if ((i & 31) == 0 && (i >> 5) < HID_WORDS) g_hid_bits[i >> 5] = bits;
    }
    {   // sensory spike bitmask
        int pred = 0;
        if (i < N_SENS) {
            float m = 0.9f * s_mem[i] + 5.0f * s_in[i];
            pred = (m > 1.0f);
        }
        uint32_t bits = __ballot_sync(0xFFFFFFFFu, pred);
        if ((i & 31) == 0 && (i >> 5) < SENS_WORDS) g_sens_bits[i >> 5] = bits;
    }
}

// ---------------------------------------------------------------------------
// K2: role-split edge kernel. 592 co-resident blocks:
//   474 stream HH (192 MB), 118 stream SH (48 MB) — 4:1 matches byte ratio.
// Dense streaming both roles: 3 independent LDG.128/iter, smem bitmask
// gates predicated atomics.
// ---------------------------------------------------------------------------
__global__ void __launch_bounds__(ETPB, 4)
k_edges(const int4* __restrict__ sh_pre,
        const int4* __restrict__ sh_post,
        const float4* __restrict__ sh_w,
        const int4* __restrict__ hh_pre,
        const int4* __restrict__ hh_post,
        const float4* __restrict__ hh_w) {
    extern __shared__ uint32_t bits[];     // 50 KB
    const int b = blockIdx.x;
    const bool is_hh = (b < N_HH_BLK);

    if (is_hh) {
        for (int i = threadIdx.x; i < HID_WORDS; i += blockDim.x)
            bits[i] = g_hid_bits[i];
        __syncthreads();

        const int stride = N_HH_BLK * ETPB;
        for (int t = b * ETPB + threadIdx.x; t < G_HH; t += stride) {
            int4 p = __ldcs(&hh_pre[t]);
            int4 q = __ldcs(&hh_post[t]);
            float4 wv = __ldcs(&hh_w[t]);
            uint32_t b0 = (bits[p.x >> 5] >> (p.x & 31)) & 1u;
            uint32_t b1 = (bits[p.y >> 5] >> (p.y & 31)) & 1u;
            uint32_t b2 = (bits[p.z >> 5] >> (p.z & 31)) & 1u;
            uint32_t b3 = (bits[p.w >> 5] >> (p.w & 31)) & 1u;
            if (b0) atomicAdd(&g_hid_in[q.x], 0.5f * wv.x);
            if (b1) atomicAdd(&g_hid_in[q.y], 0.5f * wv.y);
            if (b2) atomicAdd(&g_hid_in[q.z], 0.5f * wv.z);
            if (b3) atomicAdd(&g_hid_in[q.w], 0.5f * wv.w);
        }
    } else {
        for (int i = threadIdx.x; i < SENS_WORDS; i += blockDim.x)
            bits[i] = g_sens_bits[i];
        __syncthreads();

        const int rank = b - N_HH_BLK;                // 0..117
        const int stride = N_SH_BLK * ETPB;
        for (int t = rank * ETPB + threadIdx.x; t < G_SH; t += stride) {
            int4 p = __ldcs(&sh_pre[t]);
            int4 q = __ldcs(&sh_post[t]);
            float4 wv = __ldcs(&sh_w[t]);
            uint32_t b0 = (bits[p.x >> 5] >> (p.x & 31)) & 1u;
            uint32_t b1 = (bits[p.y >> 5] >> (p.y & 31)) & 1u;
            uint32_t b2 = (bits[p.z >> 5] >> (p.z & 31)) & 1u;
            uint32_t b3 = (bits[p.w >> 5] >> (p.w & 31)) & 1u;
            if (b0) atomicAdd(&g_hid_in[q.x], wv.x);
            if (b1) atomicAdd(&g_hid_in[q.y], wv.y);
            if (b2) atomicAdd(&g_hid_in[q.z], wv.z);
            if (b3) atomicAdd(&g_hid_in[q.w], wv.w);
        }
    }
}

// ---------------------------------------------------------------------------
// K3: HM edges -> mot_in, hidden spike computed inline (proven R7 form)
// ---------------------------------------------------------------------------
__global__ void k_hm(const float* __restrict__ h_mem,
                     const int4* __restrict__ pre,
                     const int4* __restrict__ post,
                     const float4* __restrict__ w) {
    int t = blockIdx.x * blockDim.x + threadIdx.x;
    if (t >= E_HM / 4) return;
    int4 p = __ldcs(&pre[t]);
    int4 q = __ldcs(&post[t]);
    float4 wv = __ldcs(&w[t]);
    bool s0 = 0.9f * __ldg(&h_mem[p.x]) + 5.0f * g_hid_in[p.x] > 1.0f;
    bool s1 = 0.9f * __ldg(&h_mem[p.y]) + 5.0f * g_hid_in[p.y] > 1.0f;
    bool s2 = 0.9f * __ldg(&h_mem[p.z]) + 5.0f * g_hid_in[p.z] > 1.0f;
    bool s3 = 0.9f * __ldg(&h_mem[p.w]) + 5.0f * g_hid_in[p.w] > 1.0f;
    if (s0) atomicAdd(&g_mot_in[q.x], wv.x);
    if (s1) atomicAdd(&g_mot_in[q.y], wv.y);
    if (s2) atomicAdd(&g_mot_in[q.z], wv.z);
    if (s3) atomicAdd(&g_mot_in[q.w], wv.w);
}

// ---------------------------------------------------------------------------
// K4: motor LIF -> output
// ---------------------------------------------------------------------------
__global__ void k_mot(const float* __restrict__ m_mem, float* __restrict__ out) {
    int i = blockIdx.x * blockDim.x + threadIdx.x;
    if (i >= N_MOT) return;
    float m = 0.9f * m_mem[i] + 20.0f * g_mot_in[i];
    out[i] = (m > 1.0f) ? 1.0f : 0.0f;
}

extern "C" void kernel_launch(void* const* d_in, const int* in_sizes, int n_in,
                              void* d_out, int out_size) {
    const float* sensory_input     = (const float*)d_in[0];
    const float* sensory_mem       = (const float*)d_in[1];
    const float* hidden_mem        = (const float*)d_in[2];
    const float* motor_mem         = (const float*)d_in[3];
    const float* hidden_prev_spike = (const float*)d_in[4];
    const float* w_sh              = (const float*)d_in[5];
    const float* w_hh              = (const float*)d_in[6];
    const float* w_hm              = (const float*)d_in[7];
    const int*   sh_pre            = (const int*)d_in[8];
    const int*   sh_post           = (const int*)d_in[9];
    const int*   hh_pre            = (const int*)d_in[10];
    const int*   hh_post           = (const int*)d_in[11];
    const int*   hm_pre            = (const int*)d_in[12];
    const int*   hm_post           = (const int*)d_in[13];
    float* out = (float*)d_out;

    static bool once = false;
    const int smem = HID_WORDS * sizeof(uint32_t);  // 50000 bytes
    if (!once) {
        cudaFuncSetAttribute(k_edges,
                             cudaFuncAttributeMaxDynamicSharedMemorySize, smem);
        once = true;
    }

    k_init<<<(N_HID + 255) / 256, 256>>>(sensory_input, sensory_mem,
                                         hidden_prev_spike);

    k_edges<<<EGRID, ETPB, smem>>>(
        (const int4*)sh_pre, (const int4*)sh_post, (const float4*)w_sh,
        (const int4*)hh_pre, (const int4*)hh_post, (const float4*)w_hh);

    k_hm<<<(E_HM / 4 + 255) / 256, 256>>>(hidden_mem,
                                          (const int4*)hm_pre,
                                          (const int4*)hm_post,
                                          (const float4*)w_hm);

    k_mot<<<(N_MOT + 255) / 256, 256>>>(motor_mem, out);
}

// round 12
// speedup vs baseline: 1.7889x; 1.0815x over previous
#include <cuda_runtime.h>
#include <stdint.h>

#define N_SENS 10000
#define N_HID  400000
#define N_MOT  1000
#define E_SH   4000000
#define E_HH   16000000
#define E_HM   400000

#define SENS_WORDS 313      // ceil(10000/32)
#define HID_WORDS  12500    // 400000/32

#define G_SH (E_SH / 4)     // 1,000,000 int4 groups
#define G_HH (E_HH / 4)     // 4,000,000
#define G_HM (E_HM / 4)     // 100,000

#define EGRID 592           // 148 SMs x 4 blocks, all co-resident
#define ETPB  512
#define N_HH_BLK 400        // ~105MB : 48MB after conditional post/w loads
#define N_SH_BLK (EGRID - N_HH_BLK)

// Scratch (__device__ globals; allocation-free rule)
__device__ uint32_t g_sens_bits[SENS_WORDS];
__device__ uint32_t g_hid_bits[HID_WORDS];
__device__ float    g_hid_in[N_HID];
__device__ float    g_mot_in[N_MOT];
__device__ unsigned long long g_hm_done;   // monotonic; never reset

// ---------------------------------------------------------------------------
// K1: zero accumulators, build sensory + hidden-prev spike bitmasks
// ---------------------------------------------------------------------------
__global__ void k_init(const float* __restrict__ s_in,
                       const float* __restrict__ s_mem,
                       const float* __restrict__ prev_spk) {
    int i = blockIdx.x * blockDim.x + threadIdx.x;

    if (i < N_HID) g_hid_in[i] = 0.0f;
    if (i < N_MOT) g_mot_in[i] = 0.0f;

    {   // hidden prev-spike bitmask (grid is multiple of 32 threads)
        int pred = (i < N_HID) ? (prev_spk[i] != 0.0f) : 0;
        uint32_t bits = __ballot_sync(0xFFFFFFFFu, pred);
        if ((i & 31) == 0 && (i >> 5) < HID_WORDS) g_hid_bits[i >> 5] = bits;
    }
    {   // sensory spike bitmask
        int pred = 0;
        if (i < N_SENS) {
            float m = 0.9f * s_mem[i] + 5.0f * s_in[i];
            pred = (m > 1.0f);
        }
        uint32_t bits = __ballot_sync(0xFFFFFFFFu, pred);
        if ((i & 31) == 0 && (i >> 5) < SENS_WORDS) g_sens_bits[i >> 5] = bits;
    }
}

// ---------------------------------------------------------------------------
// K2: role-split edge kernel.
//   HH role (400 blocks): software-pipelined pre stream (prefetch t+stride),
//     post/w loaded ONLY for live groups (~18.5%) -> ~105 MB instead of 192.
//   SH role (192 blocks): dense streaming (89% live), proven form.
// ---------------------------------------------------------------------------
__global__ void __launch_bounds__(ETPB, 4)
k_edges(const int4* __restrict__ sh_pre,
        const int4* __restrict__ sh_post,
        const float4* __restrict__ sh_w,
        const int4* __restrict__ hh_pre,
        const int4* __restrict__ hh_post,
        const float4* __restrict__ hh_w) {
    extern __shared__ uint32_t bits[];     // 50 KB
    const int b = blockIdx.x;
    const bool is_hh = (b < N_HH_BLK);

    if (is_hh) {
        for (int i = threadIdx.x; i < HID_WORDS; i += blockDim.x)
            bits[i] = g_hid_bits[i];
        __syncthreads();

        const int stride = N_HH_BLK * ETPB;
        int t = b * ETPB + threadIdx.x;      // always < G_HH (204800 <= 4M)
        int4 p = __ldcs(&hh_pre[t]);
        while (t < G_HH) {
            const int tn = t + stride;
            int4 pn;
            if (tn < G_HH) pn = __ldcs(&hh_pre[tn]);   // prefetch next iter

            uint32_t b0 = (bits[p.x >> 5] >> (p.x & 31)) & 1u;
            uint32_t b1 = (bits[p.y >> 5] >> (p.y & 31)) & 1u;
            uint32_t b2 = (bits[p.z >> 5] >> (p.z & 31)) & 1u;
            uint32_t b3 = (bits[p.w >> 5] >> (p.w & 31)) & 1u;
            if (b0 | b1 | b2 | b3) {
                int4 q = __ldcs(&hh_post[t]);
                float4 wv = __ldcs(&hh_w[t]);
                if (b0) atomicAdd(&g_hid_in[q.x], 0.5f * wv.x);
                if (b1) atomicAdd(&g_hid_in[q.y], 0.5f * wv.y);
                if (b2) atomicAdd(&g_hid_in[q.z], 0.5f * wv.z);
                if (b3) atomicAdd(&g_hid_in[q.w], 0.5f * wv.w);
            }
            p = pn;
            t = tn;
        }
    } else {
        for (int i = threadIdx.x; i < SENS_WORDS; i += blockDim.x)
            bits[i] = g_sens_bits[i];
        __syncthreads();

        const int rank = b - N_HH_BLK;                // 0..191
        const int stride = N_SH_BLK * ETPB;
        for (int t = rank * ETPB + threadIdx.x; t < G_SH; t += stride) {
            int4 p = __ldcs(&sh_pre[t]);
            int4 q = __ldcs(&sh_post[t]);
            float4 wv = __ldcs(&sh_w[t]);
            uint32_t b0 = (bits[p.x >> 5] >> (p.x & 31)) & 1u;
            uint32_t b1 = (bits[p.y >> 5] >> (p.y & 31)) & 1u;
            uint32_t b2 = (bits[p.z >> 5] >> (p.z & 31)) & 1u;
            uint32_t b3 = (bits[p.w >> 5] >> (p.w & 31)) & 1u;
            if (b0) atomicAdd(&g_hid_in[q.x], wv.x);
            if (b1) atomicAdd(&g_hid_in[q.y], wv.y);
            if (b2) atomicAdd(&g_hid_in[q.z], wv.z);
            if (b3) atomicAdd(&g_hid_in[q.w], wv.w);
        }
    }
}

// ---------------------------------------------------------------------------
// K3: HM edges -> mot_in (inline hidden spike), THEN the last block to finish
// computes the motor LIF (threadFenceReduction pattern) — removes k_mot node.
// NOTE: no early returns; all threads reach the __syncthreads below.
// ---------------------------------------------------------------------------
#define HM_TPB  256
#define HM_GRID ((G_HM + HM_TPB - 1) / HM_TPB)    // 391

__global__ void __launch_bounds__(HM_TPB)
k_hm(const float* __restrict__ h_mem,
     const float* __restrict__ m_mem,
     const int4* __restrict__ pre,
     const int4* __restrict__ post,
     const float4* __restrict__ w,
     float* __restrict__ out) {
    const int t = blockIdx.x * blockDim.x + threadIdx.x;

    if (t < G_HM) {
        int4 p = __ldcs(&pre[t]);
        int4 q = __ldcs(&post[t]);
        float4 wv = __ldcs(&w[t]);
        bool s0 = 0.9f * __ldg(&h_mem[p.x]) + 5.0f * g_hid_in[p.x] > 1.0f;
        bool s1 = 0.9f * __ldg(&h_mem[p.y]) + 5.0f * g_hid_in[p.y] > 1.0f;
        bool s2 = 0.9f * __ldg(&h_mem[p.z]) + 5.0f * g_hid_in[p.z] > 1.0f;
        bool s3 = 0.9f * __ldg(&h_mem[p.w]) + 5.0f * g_hid_in[p.w] > 1.0f;
        if (s0) atomicAdd(&g_mot_in[q.x], wv.x);
        if (s1) atomicAdd(&g_mot_in[q.y], wv.y);
        if (s2) atomicAdd(&g_mot_in[q.z], wv.z);
        if (s3) atomicAdd(&g_mot_in[q.w], wv.w);
    }

    // last-finishing block computes motor LIF
    __shared__ bool is_last;
    __threadfence();
    __syncthreads();
    if (threadIdx.x == 0) {
        unsigned long long ticket = atomicAdd(&g_hm_done, 1ULL);
        is_last = ((ticket % (unsigned long long)gridDim.x) ==
                   (unsigned long long)(gridDim.x - 1));
    }
    __syncthreads();
    if (is_last) {
        for (int i = threadIdx.x; i < N_MOT; i += blockDim.x) {
            float m = 0.9f * __ldg(&m_mem[i]) + 20.0f * __ldcg(&g_mot_in[i]);
            out[i] = (m > 1.0f) ? 1.0f : 0.0f;
        }
    }
}

extern "C" void kernel_launch(void* const* d_in, const int* in_sizes, int n_in,
                              void* d_out, int out_size) {
    const float* sensory_input     = (const float*)d_in[0];
    const float* sensory_mem       = (const float*)d_in[1];
    const float* hidden_mem        = (const float*)d_in[2];
    const float* motor_mem         = (const float*)d_in[3];
    const float* hidden_prev_spike = (const float*)d_in[4];
    const float* w_sh              = (const float*)d_in[5];
    const float* w_hh              = (const float*)d_in[6];
    const float* w_hm              = (const float*)d_in[7];
    const int*   sh_pre            = (const int*)d_in[8];
    const int*   sh_post           = (const int*)d_in[9];
    const int*   hh_pre            = (const int*)d_in[10];
    const int*   hh_post           = (const int*)d_in[11];
    const int*   hm_pre            = (const int*)d_in[12];
    const int*   hm_post           = (const int*)d_in[13];
    float* out = (float*)d_out;

    static bool once = false;
    const int smem = HID_WORDS * sizeof(uint32_t);  // 50000 bytes
    if (!once) {
        cudaFuncSetAttribute(k_edges,
                             cudaFuncAttributeMaxDynamicSharedMemorySize, smem);
        once = true;
    }

    k_init<<<(N_HID + 255) / 256, 256>>>(sensory_input, sensory_mem,
                                         hidden_prev_spike);

    k_edges<<<EGRID, ETPB, smem>>>(
        (const int4*)sh_pre, (const int4*)sh_post, (const float4*)w_sh,
        (const int4*)hh_pre, (const int4*)hh_post, (const float4*)w_hh);

    k_hm<<<HM_GRID, HM_TPB>>>(hidden_mem, motor_mem,
                              (const int4*)hm_pre, (const int4*)hm_post,
                              (const float4*)w_hm, out);
}